// round 13
// baseline (speedup 1.0000x reference)
#include <cuda_runtime.h>
#include <cuda_fp16.h>
#include <cuda_pipeline_primitives.h>
#include <mma.h>

using namespace nvcuda;

#define NV 8192
#define DIN 256
#define FD 128
#define MAXE 640
#define HMAX 320
#define NF (NV*FD)
#define NCHK 64
#define APITCH 136
#define TILEB 34816           // 128*136*2 bytes
#define FULLMASK 0xFFFFFFFFu

// ---------------- device scratch (no runtime allocation allowed) ----------------
__device__ float  g_proj[2 * NF];              // [h][n][f] fp32
__device__ __half g_projh[2 * NF];             // [n][h][f] fp16 interleaved, 512B/node
__device__ float  g_res[NF];                   // x @ W_res^T
__device__ float  g_valsh[2 * NF];             // per-head attention outputs
__device__ unsigned short g_cols[NV * MAXE];   // CSR cols, 2 sublists/row of HMAX, bits 14/13 = sign flags
__device__ int    g_rowcnt2[2 * NV];           // per-sublist counts
__device__ float  g_ssrc[2 * NV], g_ea[2 * NV], g_ea2[2 * NV];
__device__ float  g_eb[2 * NV], g_eb2[2 * NV];
__device__ float2 g_stgt2[NV];                 // {stgt_h0, stgt_h1}
__device__ float  g_PQ[4 * NV];                // [h0P, h0Q, h1P, h1Q]
__device__ float4 g_coefpk[NV];                // {czp0, czn0, czp1, czn1}
__device__ float4 g_rowea[NV];                 // {ea0, ea20, ea1, ea21}
__device__ double g_sum[2];                    // sum, sumsq

// ---------------- K0: zero accumulators (every graph replay) ----------------
__global__ void k0_zero() {
    int i = blockIdx.x * 256 + threadIdx.x;
    if (i < 4 * NV) g_PQ[i] = 0.0f;
    if (i < 2) g_sum[i] = 0.0;
}

// ---------------- K1: fused SGEMM  C = x @ [W0 | W1 | Wres^T]  (+ fp16 epilogue) ----------------
__global__ __launch_bounds__(256) void k1_gemm(const float* __restrict__ x,
                                               const float* __restrict__ W,
                                               const float* __restrict__ Wres) {
    __shared__ float As[16][132];
    __shared__ float Bs[16][128];
    const int m0 = blockIdx.x * 128;
    const int which = blockIdx.y;
    const int tid = threadIdx.x;
    const int tx = tid & 15, ty = tid >> 4;

    float acc[8][8];
#pragma unroll
    for (int i = 0; i < 8; i++)
#pragma unroll
        for (int j = 0; j < 8; j++) acc[i][j] = 0.0f;

    const int mA = tid >> 1;
    const int kA = (tid & 1) * 8;

    for (int k0 = 0; k0 < DIN; k0 += 16) {
        {
            const float* src = x + (size_t)(m0 + mA) * DIN + k0 + kA;
            float4 v0 = *(const float4*)(src);
            float4 v1 = *(const float4*)(src + 4);
            As[kA + 0][mA] = v0.x; As[kA + 1][mA] = v0.y;
            As[kA + 2][mA] = v0.z; As[kA + 3][mA] = v0.w;
            As[kA + 4][mA] = v1.x; As[kA + 5][mA] = v1.y;
            As[kA + 6][mA] = v1.z; As[kA + 7][mA] = v1.w;
        }
        if (which < 2) {
            int k = tid >> 4, f = (tid & 15) * 8;
            const float* src = W + ((size_t)which * DIN + (k0 + k)) * FD + f;
            float4 v0 = *(const float4*)(src);
            float4 v1 = *(const float4*)(src + 4);
            *(float4*)&Bs[k][f] = v0;
            *(float4*)&Bs[k][f + 4] = v1;
        } else {
            int f = tid >> 1;
            const float* src = Wres + (size_t)f * DIN + k0 + kA;
            float4 v0 = *(const float4*)(src);
            float4 v1 = *(const float4*)(src + 4);
            Bs[kA + 0][f] = v0.x; Bs[kA + 1][f] = v0.y;
            Bs[kA + 2][f] = v0.z; Bs[kA + 3][f] = v0.w;
            Bs[kA + 4][f] = v1.x; Bs[kA + 5][f] = v1.y;
            Bs[kA + 6][f] = v1.z; Bs[kA + 7][f] = v1.w;
        }
        __syncthreads();

#pragma unroll
        for (int kk = 0; kk < 16; kk++) {
            float4 ra0 = *(const float4*)&As[kk][ty * 8];
            float4 ra1 = *(const float4*)&As[kk][ty * 8 + 4];
            float4 rb0 = *(const float4*)&Bs[kk][tx * 8];
            float4 rb1 = *(const float4*)&Bs[kk][tx * 8 + 4];
            float ra[8] = {ra0.x, ra0.y, ra0.z, ra0.w, ra1.x, ra1.y, ra1.z, ra1.w};
            float rb[8] = {rb0.x, rb0.y, rb0.z, rb0.w, rb1.x, rb1.y, rb1.z, rb1.w};
#pragma unroll
            for (int i = 0; i < 8; i++)
#pragma unroll
                for (int j = 0; j < 8; j++) acc[i][j] += ra[i] * rb[j];
        }
        __syncthreads();
    }

    float* dst = (which < 2) ? &g_proj[(size_t)which * NF] : g_res;
#pragma unroll
    for (int i = 0; i < 8; i++) {
        int row = m0 + ty * 8 + i;
        float4 w0 = make_float4(acc[i][0], acc[i][1], acc[i][2], acc[i][3]);
        float4 w1 = make_float4(acc[i][4], acc[i][5], acc[i][6], acc[i][7]);
        *(float4*)&dst[(size_t)row * FD + tx * 8]     = w0;
        *(float4*)&dst[(size_t)row * FD + tx * 8 + 4] = w1;
        if (which < 2) {
            __align__(16) __half2 hp[4];
            hp[0] = __floats2half2_rn(acc[i][0], acc[i][1]);
            hp[1] = __floats2half2_rn(acc[i][2], acc[i][3]);
            hp[2] = __floats2half2_rn(acc[i][4], acc[i][5]);
            hp[3] = __floats2half2_rn(acc[i][6], acc[i][7]);
            *(uint4*)((char*)g_projh + (size_t)row * 512 + which * 256 + tx * 16) = *(uint4*)hp;
        }
    }
}

// ---------------- K2: per-node dots + 8 exps (+ packed rowea/stgt2) ----------------
__global__ __launch_bounds__(256) void k2_scal(const float* __restrict__ asrc,
                                               const float* __restrict__ atgt) {
    int w = blockIdx.x * 8 + (threadIdx.x >> 5);
    int lane = threadIdx.x & 31;
    if (w >= 2 * NV) return;
    int h = w >> 13;
    const float* pr = &g_proj[(size_t)w * FD];
    const float* as = asrc + h * FD;
    const float* at = atgt + h * FD;
    float s1 = 0.0f, s2 = 0.0f;
#pragma unroll
    for (int j = 0; j < 4; j++) {
        float p = pr[lane + 32 * j];
        s1 += p * as[lane + 32 * j];
        s2 += p * at[lane + 32 * j];
    }
#pragma unroll
    for (int o = 16; o; o >>= 1) {
        s1 += __shfl_xor_sync(FULLMASK, s1, o);
        s2 += __shfl_xor_sync(FULLMASK, s2, o);
    }
    if (lane == 0) {
        float ea = expf(s1), ea2 = expf(0.2f * s1);
        g_ssrc[w] = s1; g_ea[w] = ea; g_ea2[w] = ea2;
        g_eb[w] = expf(s2); g_eb2[w] = expf(0.2f * s2);
        int n = w & (NV - 1);
        ((float2*)&g_rowea[n])[h] = make_float2(ea, ea2);
        ((float*)&g_stgt2[n])[h] = s2;
    }
}

// ---------------- K3: mask pass, 2 warps/row: copy-out + split CSR build ----------------
__global__ __launch_bounds__(256) void k3_mask(const float4* __restrict__ conn,
                                               float4* __restrict__ outmask) {
    int w = blockIdx.x * 8 + (threadIdx.x >> 5);   // 0..16383
    int lane = threadIdx.x & 31;
    int m = w >> 1, half = w & 1;
    const float4* src = conn + (size_t)m * (NV / 4) + half * 1024;
    float4* dst = outmask + (size_t)m * (NV / 4) + half * 1024;
    unsigned short* cols = &g_cols[(size_t)m * MAXE + half * HMAX];
    int cnt = 0;
#pragma unroll 2
    for (int it = 0; it < 32; it++) {
        int q = it * 32 + lane;
        float4 v = src[q];
        __stcs(&dst[q], v);
        unsigned b0 = __ballot_sync(FULLMASK, v.x == 0.0f);
        unsigned b1 = __ballot_sync(FULLMASK, v.y == 0.0f);
        unsigned b2 = __ballot_sync(FULLMASK, v.z == 0.0f);
        unsigned b3 = __ballot_sync(FULLMASK, v.w == 0.0f);
        unsigned lt = (1u << lane) - 1u;
        int o = cnt + __popc(b0 & lt) + __popc(b1 & lt) + __popc(b2 & lt) + __popc(b3 & lt);
        int col0 = half * 4096 + it * 128 + lane * 4;
        if (v.x == 0.0f) { if (o < HMAX) cols[o] = (unsigned short)(col0);     o++; }
        if (v.y == 0.0f) { if (o < HMAX) cols[o] = (unsigned short)(col0 + 1); o++; }
        if (v.z == 0.0f) { if (o < HMAX) cols[o] = (unsigned short)(col0 + 2); o++; }
        if (v.w == 0.0f) { if (o < HMAX) cols[o] = (unsigned short)(col0 + 3); o++; }
        cnt += __popc(b0) + __popc(b1) + __popc(b2) + __popc(b3);
    }
    if (lane == 0) g_rowcnt2[w] = min(cnt, HMAX);
}

// ---------------- K4: sign-split column sums P/Q + pack sign bits (warp per sublist) ----------------
__global__ __launch_bounds__(256) void k4_z() {
    int w = blockIdx.x * 8 + (threadIdx.x >> 5);   // 0..16383
    int lane = threadIdx.x & 31;
    int m = w >> 1, half = w & 1;
    int cnt = g_rowcnt2[w];
    float ss0 = g_ssrc[m],      ea0 = g_ea[m],      ea20 = g_ea2[m];
    float ss1 = g_ssrc[NV + m], ea1 = g_ea[NV + m], ea21 = g_ea2[NV + m];
    unsigned short* cols = &g_cols[(size_t)m * MAXE + half * HMAX];
    for (int e = lane; e < cnt; e += 32) {
        unsigned c = cols[e];
        int n = (int)c;
        float2 st = g_stgt2[n];
        if (ss0 + st.x > 0.0f) { atomicAdd(&g_PQ[n], ea0);          c |= 0x4000u; }
        else                   { atomicAdd(&g_PQ[NV + n], ea20); }
        if (ss1 + st.y > 0.0f) { atomicAdd(&g_PQ[2 * NV + n], ea1); c |= 0x2000u; }
        else                   { atomicAdd(&g_PQ[3 * NV + n], ea21); }
        cols[e] = (unsigned short)c;
    }
}

// ---------------- K5: fold Z into packed per-column coefficients ----------------
__global__ void k5_cz() {
    int n = blockIdx.x * 256 + threadIdx.x;
    if (n >= NV) return;
    float Z0 = g_eb[n] * g_PQ[n] + g_eb2[n] * g_PQ[NV + n];
    float Z1 = g_eb[NV + n] * g_PQ[2 * NV + n] + g_eb2[NV + n] * g_PQ[3 * NV + n];
    g_coefpk[n] = make_float4(0.5f * g_eb[n] / Z0,       0.5f * g_eb2[n] / Z0,
                              0.5f * g_eb[NV + n] / Z1,  0.5f * g_eb2[NV + n] / Z1);
}

// ---------------- K6: dense masked GEMM via wmma (HMMA), scatter-built A tiles ----------------
// grid (64, 2): blockIdx.x = 128-row m-tile, blockIdx.y = head. 256 threads (8 warps).
// A[128][APITCH] fp16 attn tile (scattered), B[128 nbr][APITCH] fp16 features, double-buffered.
__global__ __launch_bounds__(256) void k6_mma() {
    extern __shared__ __align__(16) __half dsm[];
    __shared__ int s_cur[128];
    __shared__ int s_cnt[128];

    const int tid = threadIdx.x, wid = tid >> 5, lane = tid & 31;
    const int mtile = blockIdx.x, h = blockIdx.y;
    const int row0 = mtile * 128;
    const unsigned flagbit = h ? 0x2000u : 0x4000u;

    __half* Ab[2] = {dsm, dsm + TILEB / 2};
    __half* Bb[2] = {dsm + TILEB, dsm + TILEB + TILEB / 2};

    wmma::fragment<wmma::accumulator, 16, 16, 16, float> facc[8];
#pragma unroll
    for (int nt = 0; nt < 8; nt++) wmma::fill_fragment(facc[nt], 0.0f);

    // ---- prepare helpers inlined ----
    // zero A[buf]
    auto zeroA = [&](int buf) {
        uint4 z = make_uint4(0u, 0u, 0u, 0u);
        __half* An = Ab[buf];
        for (int i = tid; i < TILEB / 16; i += 256)
            *(uint4*)((char*)An + (size_t)i * 16) = z;
    };
    // cp.async B[buf] for chunk c
    auto loadB = [&](int buf, int c) {
        __half* Bn = Bb[buf];
        const int k0 = c * 128;
#pragma unroll
        for (int j = 0; j < 8; j++) {
            int cid = tid + j * 256;
            int nbr = cid >> 4, c16 = cid & 15;
            const char* src = (const char*)g_projh + ((size_t)(k0 + nbr) * 256 + h * 128) * 2 + c16 * 16;
            char* dst = (char*)Bn + (size_t)nbr * (APITCH * 2) + c16 * 16;
            __pipeline_memcpy_async(dst, src, 16);
        }
        __pipeline_commit();
    };
    // scatter chunk c edges into A[buf]
    auto scatterA = [&](int buf, int c) {
        __half* An = Ab[buf];
        const int k0 = c * 128, kend = k0 + 128;
        const size_t subo = (c >= 32) ? (size_t)HMAX : 0;
        for (int r16 = 0; r16 < 16; r16++) {
            const int rl = wid * 16 + r16;
            const int grow = row0 + rl;
            int cur = s_cur[rl];
            const int cnt = s_cnt[rl];
            if (cur >= cnt) continue;
            const unsigned short* cp = g_cols + (size_t)grow * MAXE + subo;
            const float2 re2 = *(const float2*)((const char*)&g_rowea[grow] + h * 8);
            while (true) {
                int idx = cur + lane;
                bool valid = idx < cnt;
                unsigned cv = valid ? (unsigned)cp[idx] : 0u;
                int col = (int)(cv & 0x1FFFu);
                bool in = valid && (col < kend);
                unsigned bal = __ballot_sync(FULLMASK, in);
                if (in) {
                    float2 q = *(const float2*)((const char*)&g_coefpk[col] + h * 8);
                    float cf = (cv & flagbit) ? re2.x * q.x : re2.y * q.y;
                    An[rl * APITCH + (col - k0)] = __float2half_rn(cf);
                }
                int adv = __popc(bal);
                cur += adv;
                if (adv < 32 || cur >= cnt) break;
            }
            if (lane == 0) s_cur[rl] = cur;
        }
    };

    // ---- prologue: prepare chunk 0 into buffer 0 ----
    if (tid < 128) { s_cur[tid] = 0; s_cnt[tid] = g_rowcnt2[(row0 + tid) * 2]; }
    zeroA(0);
    loadB(0, 0);
    __syncthreads();
    scatterA(0, 0);

    // ---- main loop ----
    for (int ch = 0; ch < NCHK; ch++) {
        const int cur = ch & 1;
        __pipeline_wait_prior(0);       // B[cur] landed (issued before any newer group)
        __syncthreads();                // B[cur]+A[cur] visible; prev compute done -> nxt reusable
        if (ch + 1 < NCHK) {
            zeroA(cur ^ 1);
            loadB(cur ^ 1, ch + 1);
            if (ch + 1 == 32 && tid < 128) {
                s_cur[tid] = 0;
                s_cnt[tid] = g_rowcnt2[(row0 + tid) * 2 + 1];
            }
            __syncthreads();            // zero + cursor reset visible
            scatterA(cur ^ 1, ch + 1);
        }
        // compute chunk cur
        const __half* Ac = Ab[cur];
        const __half* Bc = Bb[cur];
#pragma unroll
        for (int kk = 0; kk < 8; kk++) {
            wmma::fragment<wmma::matrix_a, 16, 16, 16, __half, wmma::row_major> fa;
            wmma::load_matrix_sync(fa, Ac + (size_t)(wid * 16) * APITCH + kk * 16, APITCH);
#pragma unroll
            for (int nt = 0; nt < 8; nt++) {
                wmma::fragment<wmma::matrix_b, 16, 16, 16, __half, wmma::row_major> fb;
                wmma::load_matrix_sync(fb, Bc + (size_t)(kk * 16) * APITCH + nt * 16, APITCH);
                wmma::mma_sync(facc[nt], fa, fb, facc[nt]);
            }
        }
    }

    // ---- epilogue: store per-head result ----
    float* dbase = g_valsh + (size_t)h * NF + (size_t)(row0 + wid * 16) * FD;
#pragma unroll
    for (int nt = 0; nt < 8; nt++)
        wmma::store_matrix_sync(dbase + nt * 16, facc[nt], FD, wmma::mem_row_major);
}

// ---------------- K7: instance-norm stats over (h0 + h1) ----------------
__global__ __launch_bounds__(256) void k7_stats() {
    __shared__ double sdat[2][8];
    double s = 0.0, s2 = 0.0;
    for (int i = blockIdx.x * 256 + threadIdx.x; i < NF; i += gridDim.x * 256) {
        double v = (double)(g_valsh[i] + g_valsh[NF + i]);
        s += v; s2 += v * v;
    }
#pragma unroll
    for (int o = 16; o; o >>= 1) {
        s  += __shfl_xor_sync(FULLMASK, s, o);
        s2 += __shfl_xor_sync(FULLMASK, s2, o);
    }
    int wid = threadIdx.x >> 5, lane = threadIdx.x & 31;
    if (lane == 0) { sdat[0][wid] = s; sdat[1][wid] = s2; }
    __syncthreads();
    if (threadIdx.x == 0) {
        double t = 0.0, t2 = 0.0;
        for (int i = 0; i < 8; i++) { t += sdat[0][i]; t2 += sdat[1][i]; }
        atomicAdd(&g_sum[0], t);
        atomicAdd(&g_sum[1], t2);
    }
}

// ---------------- K8: normalize + residual + ELU ----------------
__global__ void k8_final(float* __restrict__ out) {
    int i = blockIdx.x * 256 + threadIdx.x;
    if (i >= NF) return;
    double mu_d = g_sum[0] / (double)NF;
    double var_d = g_sum[1] / (double)NF - mu_d * mu_d;
    float mu = (float)mu_d;
    float inv = rsqrtf((float)var_d + 1e-5f);
    float v = (g_valsh[i] + g_valsh[NF + i] - mu) * inv + g_res[i];
    out[i] = v > 0.0f ? v : expm1f(v);
}

// ---------------- launch ----------------
extern "C" void kernel_launch(void* const* d_in, const int* in_sizes, int n_in,
                              void* d_out, int out_size) {
    const float* x    = (const float*)d_in[0];
    const float* conn = (const float*)d_in[1];
    const float* W    = (const float*)d_in[2];
    const float* asrc = (const float*)d_in[3];
    const float* atgt = (const float*)d_in[4];
    const float* wres = (const float*)d_in[5];
    float* out = (float*)d_out;
    float* outmask = out + NF;

    const int k6_smem = 4 * TILEB;   // 2xA + 2xB = 139264 B
    static int smem_set = 0;
    if (!smem_set) {
        cudaFuncSetAttribute(k6_mma, cudaFuncAttributeMaxDynamicSharedMemorySize, k6_smem);
        smem_set = 1;
    }

    k0_zero<<<128, 256>>>();
    k1_gemm<<<dim3(64, 3), 256>>>(x, W, wres);
    k2_scal<<<2048, 256>>>(asrc, atgt);
    k3_mask<<<2048, 256>>>((const float4*)conn, (float4*)outmask);
    k4_z<<<2048, 256>>>();
    k5_cz<<<32, 256>>>();
    k6_mma<<<dim3(64, 2), 256, k6_smem>>>();
    k7_stats<<<512, 256>>>();
    k8_final<<<NF / 256, 256>>>(out);
}

// round 14
// speedup vs baseline: 2.3908x; 2.3908x over previous
#include <cuda_runtime.h>
#include <cuda_fp16.h>

#define NV 8192
#define DIN 256
#define FD 128
#define MAXE 640
#define HMAX 320
#define NF (NV*FD)
#define FULLMASK 0xFFFFFFFFu

// ---------------- device scratch (no runtime allocation allowed) ----------------
__device__ float  g_proj[2 * NF];              // [h][n][f] fp32
__device__ __half g_projh[2 * NF];             // [n][h][f] fp16 interleaved, 512B/node
__device__ float  g_res[NF];                   // x @ W_res^T
__device__ float  g_vals[NF];                  // head-mean attention output
__device__ unsigned short g_cols[NV * MAXE];   // CSR cols, 2 sublists/row of HMAX, bits 14/13 = sign flags
__device__ int    g_rowcnt2[2 * NV];           // per-sublist counts
__device__ float  g_ssrc[2 * NV], g_ea[2 * NV], g_ea2[2 * NV];
__device__ float  g_eb[2 * NV], g_eb2[2 * NV];
__device__ float2 g_stgt2[NV];                 // {stgt_h0, stgt_h1}
__device__ float  g_PQ[4 * NV];                // [h0P, h0Q, h1P, h1Q]
__device__ float4 g_coefpk[NV];                // {czp0, czn0, czp1, czn1}
__device__ float4 g_rowea[NV];                 // {ea0, ea20, ea1, ea21}
__device__ double g_sum[2];                    // sum, sumsq

// ---------------- K0: zero accumulators (every graph replay) ----------------
__global__ void k0_zero() {
    int i = blockIdx.x * 256 + threadIdx.x;
    if (i < 4 * NV) g_PQ[i] = 0.0f;
    if (i < 2) g_sum[i] = 0.0;
}

// ---------------- K1: fused SGEMM  C = x @ [W0 | W1 | Wres^T]  (+ fp16 epilogue) ----------------
__global__ __launch_bounds__(256) void k1_gemm(const float* __restrict__ x,
                                               const float* __restrict__ W,
                                               const float* __restrict__ Wres) {
    __shared__ float As[16][132];
    __shared__ float Bs[16][128];
    const int m0 = blockIdx.x * 128;
    const int which = blockIdx.y;
    const int tid = threadIdx.x;
    const int tx = tid & 15, ty = tid >> 4;

    float acc[8][8];
#pragma unroll
    for (int i = 0; i < 8; i++)
#pragma unroll
        for (int j = 0; j < 8; j++) acc[i][j] = 0.0f;

    const int mA = tid >> 1;
    const int kA = (tid & 1) * 8;

    for (int k0 = 0; k0 < DIN; k0 += 16) {
        {
            const float* src = x + (size_t)(m0 + mA) * DIN + k0 + kA;
            float4 v0 = *(const float4*)(src);
            float4 v1 = *(const float4*)(src + 4);
            As[kA + 0][mA] = v0.x; As[kA + 1][mA] = v0.y;
            As[kA + 2][mA] = v0.z; As[kA + 3][mA] = v0.w;
            As[kA + 4][mA] = v1.x; As[kA + 5][mA] = v1.y;
            As[kA + 6][mA] = v1.z; As[kA + 7][mA] = v1.w;
        }
        if (which < 2) {
            int k = tid >> 4, f = (tid & 15) * 8;
            const float* src = W + ((size_t)which * DIN + (k0 + k)) * FD + f;
            float4 v0 = *(const float4*)(src);
            float4 v1 = *(const float4*)(src + 4);
            *(float4*)&Bs[k][f] = v0;
            *(float4*)&Bs[k][f + 4] = v1;
        } else {
            int f = tid >> 1;
            const float* src = Wres + (size_t)f * DIN + k0 + kA;
            float4 v0 = *(const float4*)(src);
            float4 v1 = *(const float4*)(src + 4);
            Bs[kA + 0][f] = v0.x; Bs[kA + 1][f] = v0.y;
            Bs[kA + 2][f] = v0.z; Bs[kA + 3][f] = v0.w;
            Bs[kA + 4][f] = v1.x; Bs[kA + 5][f] = v1.y;
            Bs[kA + 6][f] = v1.z; Bs[kA + 7][f] = v1.w;
        }
        __syncthreads();

#pragma unroll
        for (int kk = 0; kk < 16; kk++) {
            float4 ra0 = *(const float4*)&As[kk][ty * 8];
            float4 ra1 = *(const float4*)&As[kk][ty * 8 + 4];
            float4 rb0 = *(const float4*)&Bs[kk][tx * 8];
            float4 rb1 = *(const float4*)&Bs[kk][tx * 8 + 4];
            float ra[8] = {ra0.x, ra0.y, ra0.z, ra0.w, ra1.x, ra1.y, ra1.z, ra1.w};
            float rb[8] = {rb0.x, rb0.y, rb0.z, rb0.w, rb1.x, rb1.y, rb1.z, rb1.w};
#pragma unroll
            for (int i = 0; i < 8; i++)
#pragma unroll
                for (int j = 0; j < 8; j++) acc[i][j] += ra[i] * rb[j];
        }
        __syncthreads();
    }

    float* dst = (which < 2) ? &g_proj[(size_t)which * NF] : g_res;
#pragma unroll
    for (int i = 0; i < 8; i++) {
        int row = m0 + ty * 8 + i;
        float4 w0 = make_float4(acc[i][0], acc[i][1], acc[i][2], acc[i][3]);
        float4 w1 = make_float4(acc[i][4], acc[i][5], acc[i][6], acc[i][7]);
        *(float4*)&dst[(size_t)row * FD + tx * 8]     = w0;
        *(float4*)&dst[(size_t)row * FD + tx * 8 + 4] = w1;
        if (which < 2) {
            __align__(16) __half2 hp[4];
            hp[0] = __floats2half2_rn(acc[i][0], acc[i][1]);
            hp[1] = __floats2half2_rn(acc[i][2], acc[i][3]);
            hp[2] = __floats2half2_rn(acc[i][4], acc[i][5]);
            hp[3] = __floats2half2_rn(acc[i][6], acc[i][7]);
            *(uint4*)((char*)g_projh + (size_t)row * 512 + which * 256 + tx * 16) = *(uint4*)hp;
        }
    }
}

// ---------------- K2: per-node dots + 8 exps (+ packed rowea/stgt2) ----------------
__global__ __launch_bounds__(256) void k2_scal(const float* __restrict__ asrc,
                                               const float* __restrict__ atgt) {
    int w = blockIdx.x * 8 + (threadIdx.x >> 5);
    int lane = threadIdx.x & 31;
    if (w >= 2 * NV) return;
    int h = w >> 13;
    const float* pr = &g_proj[(size_t)w * FD];
    const float* as = asrc + h * FD;
    const float* at = atgt + h * FD;
    float s1 = 0.0f, s2 = 0.0f;
#pragma unroll
    for (int j = 0; j < 4; j++) {
        float p = pr[lane + 32 * j];
        s1 += p * as[lane + 32 * j];
        s2 += p * at[lane + 32 * j];
    }
#pragma unroll
    for (int o = 16; o; o >>= 1) {
        s1 += __shfl_xor_sync(FULLMASK, s1, o);
        s2 += __shfl_xor_sync(FULLMASK, s2, o);
    }
    if (lane == 0) {
        float ea = expf(s1), ea2 = expf(0.2f * s1);
        g_ssrc[w] = s1; g_ea[w] = ea; g_ea2[w] = ea2;
        g_eb[w] = expf(s2); g_eb2[w] = expf(0.2f * s2);
        int n = w & (NV - 1);
        ((float2*)&g_rowea[n])[h] = make_float2(ea, ea2);
        ((float*)&g_stgt2[n])[h] = s2;
    }
}

// ---------------- K3: mask pass, 2 warps/row: copy-out + split CSR build ----------------
__global__ __launch_bounds__(256) void k3_mask(const float4* __restrict__ conn,
                                               float4* __restrict__ outmask) {
    int w = blockIdx.x * 8 + (threadIdx.x >> 5);   // 0..16383
    int lane = threadIdx.x & 31;
    int m = w >> 1, half = w & 1;
    const float4* src = conn + (size_t)m * (NV / 4) + half * 1024;
    float4* dst = outmask + (size_t)m * (NV / 4) + half * 1024;
    unsigned short* cols = &g_cols[(size_t)m * MAXE + half * HMAX];
    int cnt = 0;
#pragma unroll 2
    for (int it = 0; it < 32; it++) {              // 32 iters x 128 floats = 4096 cols
        int q = it * 32 + lane;
        float4 v = src[q];
        __stcs(&dst[q], v);
        unsigned b0 = __ballot_sync(FULLMASK, v.x == 0.0f);
        unsigned b1 = __ballot_sync(FULLMASK, v.y == 0.0f);
        unsigned b2 = __ballot_sync(FULLMASK, v.z == 0.0f);
        unsigned b3 = __ballot_sync(FULLMASK, v.w == 0.0f);
        unsigned lt = (1u << lane) - 1u;
        int o = cnt + __popc(b0 & lt) + __popc(b1 & lt) + __popc(b2 & lt) + __popc(b3 & lt);
        int col0 = half * 4096 + it * 128 + lane * 4;
        if (v.x == 0.0f) { if (o < HMAX) cols[o] = (unsigned short)(col0);     o++; }
        if (v.y == 0.0f) { if (o < HMAX) cols[o] = (unsigned short)(col0 + 1); o++; }
        if (v.z == 0.0f) { if (o < HMAX) cols[o] = (unsigned short)(col0 + 2); o++; }
        if (v.w == 0.0f) { if (o < HMAX) cols[o] = (unsigned short)(col0 + 3); o++; }
        cnt += __popc(b0) + __popc(b1) + __popc(b2) + __popc(b3);
    }
    if (lane == 0) g_rowcnt2[w] = min(cnt, HMAX);
}

// ---------------- K4: sign-split column sums P/Q + pack sign bits (warp per sublist) ----------------
__global__ __launch_bounds__(256) void k4_z() {
    int w = blockIdx.x * 8 + (threadIdx.x >> 5);   // 0..16383
    int lane = threadIdx.x & 31;
    int m = w >> 1, half = w & 1;
    int cnt = g_rowcnt2[w];
    float ss0 = g_ssrc[m],      ea0 = g_ea[m],      ea20 = g_ea2[m];
    float ss1 = g_ssrc[NV + m], ea1 = g_ea[NV + m], ea21 = g_ea2[NV + m];
    unsigned short* cols = &g_cols[(size_t)m * MAXE + half * HMAX];
    for (int e = lane; e < cnt; e += 32) {
        unsigned c = cols[e];
        int n = (int)c;
        float2 st = g_stgt2[n];
        if (ss0 + st.x > 0.0f) { atomicAdd(&g_PQ[n], ea0);          c |= 0x4000u; }
        else                   { atomicAdd(&g_PQ[NV + n], ea20); }
        if (ss1 + st.y > 0.0f) { atomicAdd(&g_PQ[2 * NV + n], ea1); c |= 0x2000u; }
        else                   { atomicAdd(&g_PQ[3 * NV + n], ea21); }
        cols[e] = (unsigned short)c;
    }
}

// ---------------- K5: fold Z into packed per-column coefficients ----------------
__global__ void k5_cz() {
    int n = blockIdx.x * 256 + threadIdx.x;
    if (n >= NV) return;
    float Z0 = g_eb[n] * g_PQ[n] + g_eb2[n] * g_PQ[NV + n];
    float Z1 = g_eb[NV + n] * g_PQ[2 * NV + n] + g_eb2[NV + n] * g_PQ[3 * NV + n];
    g_coefpk[n] = make_float4(0.5f * g_eb[n] / Z0,       0.5f * g_eb2[n] / Z0,
                              0.5f * g_eb[NV + n] / Z1,  0.5f * g_eb2[NV + n] / Z1);
}

// ---------------- K6: gather SpMM, 4 warps/row (2 per sublist), fused stats ----------------
// grid 4096 x 256: 2 rows/block, lane-split heads within each warp.
__global__ __launch_bounds__(256) void k6_spmm() {
    __shared__ float  smrg[8][128];
    __shared__ double sred[2][2];
    const int tid = threadIdx.x, wid = tid >> 5, lane = tid & 31;
    const int rl = wid >> 2, sub = (wid >> 1) & 1, par = wid & 1;
    const int row = blockIdx.x * 2 + rl;
    const int cnt = g_rowcnt2[row * 2 + sub];
    const unsigned short* __restrict__ cp = &g_cols[(size_t)row * MAXE + sub * HMAX];
    const float4 re = __ldg(&g_rowea[row]);
    const bool h1 = lane >= 16;

    float acc[8];
#pragma unroll
    for (int j = 0; j < 8; j++) acc[j] = 0.0f;

#pragma unroll 4
    for (int e = par; e < cnt; e += 2) {
        const unsigned c = cp[e];
        const int n = (int)(c & 0x1FFFu);
        const float4 q = __ldg(&g_coefpk[n]);
        const float cf = h1 ? ((c & 0x2000u) ? re.z * q.z : re.w * q.w)
                            : ((c & 0x4000u) ? re.x * q.x : re.y * q.y);
        const uint4 hv = *(const uint4*)((const char*)g_projh + (size_t)n * 512 + lane * 16);
        const half2* hp = (const half2*)&hv;
#pragma unroll
        for (int j = 0; j < 4; j++) {
            float2 f = __half22float2(hp[j]);
            acc[2 * j]     += cf * f.x;
            acc[2 * j + 1] += cf * f.y;
        }
    }
    // merge head1 partials (lanes 16..31) into lanes 0..15, park in smem
#pragma unroll
    for (int j = 0; j < 8; j++) acc[j] += __shfl_down_sync(FULLMASK, acc[j], 16);
    if (lane < 16) {
#pragma unroll
        for (int j = 0; j < 8; j++) smrg[wid][lane * 8 + j] = acc[j];
    }
    __syncthreads();

    double s = 0.0, s2 = 0.0;
    if ((wid & 3) == 0) {                          // warps 0 and 4 finalize their row
        if (lane < 16) {
            float v[8];
#pragma unroll
            for (int j = 0; j < 8; j++) {
                int idx = lane * 8 + j;
                v[j] = smrg[wid][idx] + smrg[wid + 1][idx] + smrg[wid + 2][idx] + smrg[wid + 3][idx];
                double dv = (double)v[j];
                s += dv; s2 += dv * dv;
            }
            float* dp = &g_vals[(size_t)row * FD + lane * 8];
            *(float4*)dp       = make_float4(v[0], v[1], v[2], v[3]);
            *(float4*)(dp + 4) = make_float4(v[4], v[5], v[6], v[7]);
        }
#pragma unroll
        for (int o = 8; o; o >>= 1) {
            s  += __shfl_down_sync(FULLMASK, s, o);
            s2 += __shfl_down_sync(FULLMASK, s2, o);
        }
        if (lane == 0) { sred[0][rl] = s; sred[1][rl] = s2; }
    }
    __syncthreads();
    if (tid == 0) {
        atomicAdd(&g_sum[0], sred[0][0] + sred[0][1]);
        atomicAdd(&g_sum[1], sred[1][0] + sred[1][1]);
    }
}

// ---------------- K8: normalize + residual + ELU ----------------
__global__ void k8_final(float* __restrict__ out) {
    int i = blockIdx.x * 256 + threadIdx.x;
    if (i >= NF) return;
    double mu_d = g_sum[0] / (double)NF;
    double var_d = g_sum[1] / (double)NF - mu_d * mu_d;
    float mu = (float)mu_d;
    float inv = rsqrtf((float)var_d + 1e-5f);
    float v = (g_vals[i] - mu) * inv + g_res[i];
    out[i] = v > 0.0f ? v : expm1f(v);
}

// ---------------- launch: forked capture (GEMM branch ‖ mask branch), k6 unchanged ----------------
extern "C" void kernel_launch(void* const* d_in, const int* in_sizes, int n_in,
                              void* d_out, int out_size) {
    const float* x    = (const float*)d_in[0];
    const float* conn = (const float*)d_in[1];
    const float* W    = (const float*)d_in[2];
    const float* asrc = (const float*)d_in[3];
    const float* atgt = (const float*)d_in[4];
    const float* wres = (const float*)d_in[5];
    float* out = (float*)d_out;
    float* outmask = out + NF;

    static cudaStream_t sA = nullptr, sB = nullptr;
    static cudaEvent_t evF = nullptr, evA = nullptr, evB = nullptr;
    if (!sA) {
        cudaStreamCreateWithFlags(&sA, cudaStreamNonBlocking);
        cudaStreamCreateWithFlags(&sB, cudaStreamNonBlocking);
        cudaEventCreateWithFlags(&evF, cudaEventDisableTiming);
        cudaEventCreateWithFlags(&evA, cudaEventDisableTiming);
        cudaEventCreateWithFlags(&evB, cudaEventDisableTiming);
    }

    // fork
    cudaEventRecord(evF, 0);
    cudaStreamWaitEvent(sA, evF, 0);
    cudaStreamWaitEvent(sB, evF, 0);

    // branch A: GEMM + per-node scalars (compute-bound)
    k1_gemm<<<dim3(64, 3), 256, 0, sA>>>(x, W, wres);
    k2_scal<<<2048, 256, 0, sA>>>(asrc, atgt);
    cudaEventRecord(evA, sA);

    // branch B: zero + mask stream (DRAM-bound)
    k0_zero<<<128, 256, 0, sB>>>();
    k3_mask<<<2048, 256, 0, sB>>>((const float4*)conn, (float4*)outmask);
    cudaEventRecord(evB, sB);

    // join on legacy stream
    cudaStreamWaitEvent(0, evA, 0);
    cudaStreamWaitEvent(0, evB, 0);

    k4_z<<<2048, 256>>>();
    k5_cz<<<32, 256>>>();
    k6_spmm<<<4096, 256>>>();
    k8_final<<<NF / 256, 256>>>(out);
}

// round 15
// speedup vs baseline: 2.4153x; 1.0103x over previous
#include <cuda_runtime.h>
#include <cuda_fp16.h>

#define NV 8192
#define DIN 256
#define FD 128
#define MAXE 640
#define HMAX 320
#define NF (NV*FD)
#define FULLMASK 0xFFFFFFFFu

// ---------------- device scratch (no runtime allocation allowed) ----------------
__device__ float  g_proj[2 * NF];              // [h][n][f] fp32
__device__ __half g_projh[2 * NF];             // [n][h][f] fp16 interleaved, 512B/node
__device__ float  g_res[NF];                   // x @ W_res^T
__device__ float  g_vals[NF];                  // head-mean attention output
__device__ unsigned short g_cols[NV * MAXE];   // CSR cols, 2 sublists/row of HMAX, bits 14/13 = sign flags
__device__ int    g_rowcnt2[2 * NV];           // per-sublist counts
__device__ float  g_ssrc[2 * NV], g_ea[2 * NV], g_ea2[2 * NV];
__device__ float  g_eb[2 * NV], g_eb2[2 * NV];
__device__ float2 g_stgt2[NV];                 // {stgt_h0, stgt_h1}
__device__ float  g_PQ[4 * NV];                // [h0P, h0Q, h1P, h1Q]
__device__ float4 g_coefpk[NV];                // {czp0, czn0, czp1, czn1}
__device__ float4 g_rowea[NV];                 // {ea0, ea20, ea1, ea21}
__device__ double g_sum[2];                    // sum, sumsq

// ---------------- K0: zero accumulators (every graph replay) ----------------
__global__ void k0_zero() {
    int i = blockIdx.x * 256 + threadIdx.x;
    if (i < 4 * NV) g_PQ[i] = 0.0f;
    if (i < 2) g_sum[i] = 0.0;
}

// ---------------- K1: fused SGEMM  C = x @ [W0 | W1 | Wres^T]  (+ fp16 epilogue) ----------------
__global__ __launch_bounds__(256) void k1_gemm(const float* __restrict__ x,
                                               const float* __restrict__ W,
                                               const float* __restrict__ Wres) {
    __shared__ float As[16][132];
    __shared__ float Bs[16][128];
    const int m0 = blockIdx.x * 128;
    const int which = blockIdx.y;
    const int tid = threadIdx.x;
    const int tx = tid & 15, ty = tid >> 4;

    float acc[8][8];
#pragma unroll
    for (int i = 0; i < 8; i++)
#pragma unroll
        for (int j = 0; j < 8; j++) acc[i][j] = 0.0f;

    const int mA = tid >> 1;
    const int kA = (tid & 1) * 8;

    for (int k0 = 0; k0 < DIN; k0 += 16) {
        {
            const float* src = x + (size_t)(m0 + mA) * DIN + k0 + kA;
            float4 v0 = *(const float4*)(src);
            float4 v1 = *(const float4*)(src + 4);
            As[kA + 0][mA] = v0.x; As[kA + 1][mA] = v0.y;
            As[kA + 2][mA] = v0.z; As[kA + 3][mA] = v0.w;
            As[kA + 4][mA] = v1.x; As[kA + 5][mA] = v1.y;
            As[kA + 6][mA] = v1.z; As[kA + 7][mA] = v1.w;
        }
        if (which < 2) {
            int k = tid >> 4, f = (tid & 15) * 8;
            const float* src = W + ((size_t)which * DIN + (k0 + k)) * FD + f;
            float4 v0 = *(const float4*)(src);
            float4 v1 = *(const float4*)(src + 4);
            *(float4*)&Bs[k][f] = v0;
            *(float4*)&Bs[k][f + 4] = v1;
        } else {
            int f = tid >> 1;
            const float* src = Wres + (size_t)f * DIN + k0 + kA;
            float4 v0 = *(const float4*)(src);
            float4 v1 = *(const float4*)(src + 4);
            Bs[kA + 0][f] = v0.x; Bs[kA + 1][f] = v0.y;
            Bs[kA + 2][f] = v0.z; Bs[kA + 3][f] = v0.w;
            Bs[kA + 4][f] = v1.x; Bs[kA + 5][f] = v1.y;
            Bs[kA + 6][f] = v1.z; Bs[kA + 7][f] = v1.w;
        }
        __syncthreads();

#pragma unroll
        for (int kk = 0; kk < 16; kk++) {
            float4 ra0 = *(const float4*)&As[kk][ty * 8];
            float4 ra1 = *(const float4*)&As[kk][ty * 8 + 4];
            float4 rb0 = *(const float4*)&Bs[kk][tx * 8];
            float4 rb1 = *(const float4*)&Bs[kk][tx * 8 + 4];
            float ra[8] = {ra0.x, ra0.y, ra0.z, ra0.w, ra1.x, ra1.y, ra1.z, ra1.w};
            float rb[8] = {rb0.x, rb0.y, rb0.z, rb0.w, rb1.x, rb1.y, rb1.z, rb1.w};
#pragma unroll
            for (int i = 0; i < 8; i++)
#pragma unroll
                for (int j = 0; j < 8; j++) acc[i][j] += ra[i] * rb[j];
        }
        __syncthreads();
    }

    float* dst = (which < 2) ? &g_proj[(size_t)which * NF] : g_res;
#pragma unroll
    for (int i = 0; i < 8; i++) {
        int row = m0 + ty * 8 + i;
        float4 w0 = make_float4(acc[i][0], acc[i][1], acc[i][2], acc[i][3]);
        float4 w1 = make_float4(acc[i][4], acc[i][5], acc[i][6], acc[i][7]);
        *(float4*)&dst[(size_t)row * FD + tx * 8]     = w0;
        *(float4*)&dst[(size_t)row * FD + tx * 8 + 4] = w1;
        if (which < 2) {
            __align__(16) __half2 hp[4];
            hp[0] = __floats2half2_rn(acc[i][0], acc[i][1]);
            hp[1] = __floats2half2_rn(acc[i][2], acc[i][3]);
            hp[2] = __floats2half2_rn(acc[i][4], acc[i][5]);
            hp[3] = __floats2half2_rn(acc[i][6], acc[i][7]);
            *(uint4*)((char*)g_projh + (size_t)row * 512 + which * 256 + tx * 16) = *(uint4*)hp;
        }
    }
}

// ---------------- K2: per-node dots + 8 exps (+ packed rowea/stgt2) ----------------
__global__ __launch_bounds__(256) void k2_scal(const float* __restrict__ asrc,
                                               const float* __restrict__ atgt) {
    int w = blockIdx.x * 8 + (threadIdx.x >> 5);
    int lane = threadIdx.x & 31;
    if (w >= 2 * NV) return;
    int h = w >> 13;
    const float* pr = &g_proj[(size_t)w * FD];
    const float* as = asrc + h * FD;
    const float* at = atgt + h * FD;
    float s1 = 0.0f, s2 = 0.0f;
#pragma unroll
    for (int j = 0; j < 4; j++) {
        float p = pr[lane + 32 * j];
        s1 += p * as[lane + 32 * j];
        s2 += p * at[lane + 32 * j];
    }
#pragma unroll
    for (int o = 16; o; o >>= 1) {
        s1 += __shfl_xor_sync(FULLMASK, s1, o);
        s2 += __shfl_xor_sync(FULLMASK, s2, o);
    }
    if (lane == 0) {
        float ea = expf(s1), ea2 = expf(0.2f * s1);
        g_ssrc[w] = s1; g_ea[w] = ea; g_ea2[w] = ea2;
        g_eb[w] = expf(s2); g_eb2[w] = expf(0.2f * s2);
        int n = w & (NV - 1);
        ((float2*)&g_rowea[n])[h] = make_float2(ea, ea2);
        ((float*)&g_stgt2[n])[h] = s2;
    }
}

// ---------------- K3: mask pass, 2 warps/row, 4 front-batched loads ----------------
__global__ __launch_bounds__(256) void k3_mask(const float4* __restrict__ conn,
                                               float4* __restrict__ outmask) {
    int w = blockIdx.x * 8 + (threadIdx.x >> 5);   // 0..16383
    int lane = threadIdx.x & 31;
    int m = w >> 1, half = w & 1;
    const float4* src = conn + (size_t)m * (NV / 4) + half * 1024;
    float4* dst = outmask + (size_t)m * (NV / 4) + half * 1024;
    unsigned short* cols = &g_cols[(size_t)m * MAXE + half * HMAX];
    int cnt = 0;
    for (int it = 0; it < 8; it++) {               // 8 outer x 4 batched x 128 floats
        float4 v[4];
#pragma unroll
        for (int j = 0; j < 4; j++) v[j] = src[it * 128 + j * 32 + lane];
#pragma unroll
        for (int j = 0; j < 4; j++) __stcs(&dst[it * 128 + j * 32 + lane], v[j]);
#pragma unroll
        for (int j = 0; j < 4; j++) {
            unsigned b0 = __ballot_sync(FULLMASK, v[j].x == 0.0f);
            unsigned b1 = __ballot_sync(FULLMASK, v[j].y == 0.0f);
            unsigned b2 = __ballot_sync(FULLMASK, v[j].z == 0.0f);
            unsigned b3 = __ballot_sync(FULLMASK, v[j].w == 0.0f);
            unsigned lt = (1u << lane) - 1u;
            int o = cnt + __popc(b0 & lt) + __popc(b1 & lt) + __popc(b2 & lt) + __popc(b3 & lt);
            int col0 = half * 4096 + it * 512 + j * 128 + lane * 4;
            if (v[j].x == 0.0f) { if (o < HMAX) cols[o] = (unsigned short)(col0);     o++; }
            if (v[j].y == 0.0f) { if (o < HMAX) cols[o] = (unsigned short)(col0 + 1); o++; }
            if (v[j].z == 0.0f) { if (o < HMAX) cols[o] = (unsigned short)(col0 + 2); o++; }
            if (v[j].w == 0.0f) { if (o < HMAX) cols[o] = (unsigned short)(col0 + 3); o++; }
            cnt += __popc(b0) + __popc(b1) + __popc(b2) + __popc(b3);
        }
    }
    if (lane == 0) g_rowcnt2[w] = min(cnt, HMAX);
}

// ---------------- K4: sign-split column sums P/Q + pack sign bits (warp per sublist) ----------------
__global__ __launch_bounds__(256) void k4_z() {
    int w = blockIdx.x * 8 + (threadIdx.x >> 5);   // 0..16383
    int lane = threadIdx.x & 31;
    int m = w >> 1, half = w & 1;
    int cnt = g_rowcnt2[w];
    float ss0 = g_ssrc[m],      ea0 = g_ea[m],      ea20 = g_ea2[m];
    float ss1 = g_ssrc[NV + m], ea1 = g_ea[NV + m], ea21 = g_ea2[NV + m];
    unsigned short* cols = &g_cols[(size_t)m * MAXE + half * HMAX];
    for (int e = lane; e < cnt; e += 32) {
        unsigned c = cols[e];
        int n = (int)c;
        float2 st = g_stgt2[n];
        if (ss0 + st.x > 0.0f) { atomicAdd(&g_PQ[n], ea0);          c |= 0x4000u; }
        else                   { atomicAdd(&g_PQ[NV + n], ea20); }
        if (ss1 + st.y > 0.0f) { atomicAdd(&g_PQ[2 * NV + n], ea1); c |= 0x2000u; }
        else                   { atomicAdd(&g_PQ[3 * NV + n], ea21); }
        cols[e] = (unsigned short)c;
    }
}

// ---------------- K5: fold Z into packed per-column coefficients ----------------
__global__ void k5_cz() {
    int n = blockIdx.x * 256 + threadIdx.x;
    if (n >= NV) return;
    float Z0 = g_eb[n] * g_PQ[n] + g_eb2[n] * g_PQ[NV + n];
    float Z1 = g_eb[NV + n] * g_PQ[2 * NV + n] + g_eb2[NV + n] * g_PQ[3 * NV + n];
    g_coefpk[n] = make_float4(0.5f * g_eb[n] / Z0,       0.5f * g_eb2[n] / Z0,
                              0.5f * g_eb[NV + n] / Z1,  0.5f * g_eb2[NV + n] / Z1);
}

// ---------------- K6: gather SpMM, 4 warps/row (2 per sublist), fused stats ----------------
// grid 4096 x 256: 2 rows/block, lane-split heads within each warp.
__global__ __launch_bounds__(256) void k6_spmm() {
    __shared__ float  smrg[8][128];
    __shared__ double sred[2][2];
    const int tid = threadIdx.x, wid = tid >> 5, lane = tid & 31;
    const int rl = wid >> 2, sub = (wid >> 1) & 1, par = wid & 1;
    const int row = blockIdx.x * 2 + rl;
    const int cnt = g_rowcnt2[row * 2 + sub];
    const unsigned short* __restrict__ cp = &g_cols[(size_t)row * MAXE + sub * HMAX];
    const float4 re = __ldg(&g_rowea[row]);
    const bool h1 = lane >= 16;

    float acc[8];
#pragma unroll
    for (int j = 0; j < 8; j++) acc[j] = 0.0f;

#pragma unroll 4
    for (int e = par; e < cnt; e += 2) {
        const unsigned c = cp[e];
        const int n = (int)(c & 0x1FFFu);
        const float4 q = __ldg(&g_coefpk[n]);
        const float cf = h1 ? ((c & 0x2000u) ? re.z * q.z : re.w * q.w)
                            : ((c & 0x4000u) ? re.x * q.x : re.y * q.y);
        const uint4 hv = *(const uint4*)((const char*)g_projh + (size_t)n * 512 + lane * 16);
        const half2* hp = (const half2*)&hv;
#pragma unroll
        for (int j = 0; j < 4; j++) {
            float2 f = __half22float2(hp[j]);
            acc[2 * j]     += cf * f.x;
            acc[2 * j + 1] += cf * f.y;
        }
    }
    // merge head1 partials (lanes 16..31) into lanes 0..15, park in smem
#pragma unroll
    for (int j = 0; j < 8; j++) acc[j] += __shfl_down_sync(FULLMASK, acc[j], 16);
    if (lane < 16) {
#pragma unroll
        for (int j = 0; j < 8; j++) smrg[wid][lane * 8 + j] = acc[j];
    }
    __syncthreads();

    double s = 0.0, s2 = 0.0;
    if ((wid & 3) == 0) {                          // warps 0 and 4 finalize their row
        if (lane < 16) {
            float v[8];
#pragma unroll
            for (int j = 0; j < 8; j++) {
                int idx = lane * 8 + j;
                v[j] = smrg[wid][idx] + smrg[wid + 1][idx] + smrg[wid + 2][idx] + smrg[wid + 3][idx];
                double dv = (double)v[j];
                s += dv; s2 += dv * dv;
            }
            float* dp = &g_vals[(size_t)row * FD + lane * 8];
            *(float4*)dp       = make_float4(v[0], v[1], v[2], v[3]);
            *(float4*)(dp + 4) = make_float4(v[4], v[5], v[6], v[7]);
        }
#pragma unroll
        for (int o = 8; o; o >>= 1) {
            s  += __shfl_down_sync(FULLMASK, s, o);
            s2 += __shfl_down_sync(FULLMASK, s2, o);
        }
        if (lane == 0) { sred[0][rl] = s; sred[1][rl] = s2; }
    }
    __syncthreads();
    if (tid == 0) {
        atomicAdd(&g_sum[0], sred[0][0] + sred[0][1]);
        atomicAdd(&g_sum[1], sred[1][0] + sred[1][1]);
    }
}

// ---------------- K8: normalize + residual + ELU ----------------
__global__ void k8_final(float* __restrict__ out) {
    int i = blockIdx.x * 256 + threadIdx.x;
    if (i >= NF) return;
    double mu_d = g_sum[0] / (double)NF;
    double var_d = g_sum[1] / (double)NF - mu_d * mu_d;
    float mu = (float)mu_d;
    float inv = rsqrtf((float)var_d + 1e-5f);
    float v = (g_vals[i] - mu) * inv + g_res[i];
    out[i] = v > 0.0f ? v : expm1f(v);
}

// ---------------- launch: forked capture (GEMM branch ‖ mask branch) ----------------
extern "C" void kernel_launch(void* const* d_in, const int* in_sizes, int n_in,
                              void* d_out, int out_size) {
    const float* x    = (const float*)d_in[0];
    const float* conn = (const float*)d_in[1];
    const float* W    = (const float*)d_in[2];
    const float* asrc = (const float*)d_in[3];
    const float* atgt = (const float*)d_in[4];
    const float* wres = (const float*)d_in[5];
    float* out = (float*)d_out;
    float* outmask = out + NF;

    static cudaStream_t sA = nullptr, sB = nullptr;
    static cudaEvent_t evF = nullptr, evA = nullptr, evB = nullptr;
    if (!sA) {
        cudaStreamCreateWithFlags(&sA, cudaStreamNonBlocking);
        cudaStreamCreateWithFlags(&sB, cudaStreamNonBlocking);
        cudaEventCreateWithFlags(&evF, cudaEventDisableTiming);
        cudaEventCreateWithFlags(&evA, cudaEventDisableTiming);
        cudaEventCreateWithFlags(&evB, cudaEventDisableTiming);
    }

    // fork
    cudaEventRecord(evF, 0);
    cudaStreamWaitEvent(sA, evF, 0);
    cudaStreamWaitEvent(sB, evF, 0);

    // branch A: GEMM + per-node scalars (compute-bound)
    k1_gemm<<<dim3(64, 3), 256, 0, sA>>>(x, W, wres);
    k2_scal<<<2048, 256, 0, sA>>>(asrc, atgt);
    cudaEventRecord(evA, sA);

    // branch B: zero + mask stream (DRAM-bound)
    k0_zero<<<128, 256, 0, sB>>>();
    k3_mask<<<2048, 256, 0, sB>>>((const float4*)conn, (float4*)outmask);
    cudaEventRecord(evB, sB);

    // join on legacy stream
    cudaStreamWaitEvent(0, evA, 0);
    cudaStreamWaitEvent(0, evB, 0);

    k4_z<<<2048, 256>>>();
    k5_cz<<<32, 256>>>();
    k6_spmm<<<4096, 256>>>();
    k8_final<<<NF / 256, 256>>>(out);
}

// round 16
// speedup vs baseline: 2.5123x; 1.0401x over previous
#include <cuda_runtime.h>
#include <cuda_fp16.h>

#define NV 8192
#define DIN 256
#define FD 128
#define MAXE 640
#define HMAX 320
#define NF (NV*FD)
#define FULLMASK 0xFFFFFFFFu

// ---------------- device scratch (no runtime allocation allowed) ----------------
__device__ float  g_proj[2 * NF];              // [h][n][f] fp32
__device__ __half g_projh[2 * NF];             // [n][h][f] fp16 interleaved, 512B/node
__device__ float  g_res[NF];                   // x @ W_res^T
__device__ float  g_vals[NF];                  // head-mean attention output
__device__ unsigned short g_cols[NV * MAXE];   // CSR cols, 2 sublists/row of HMAX, bits 14/13 = sign flags
__device__ int    g_rowcnt2[2 * NV];           // per-sublist counts
__device__ float  g_ssrc[2 * NV], g_ea[2 * NV], g_ea2[2 * NV];
__device__ float  g_eb[2 * NV], g_eb2[2 * NV];
__device__ float2 g_stgt2[NV];                 // {stgt_h0, stgt_h1}
__device__ float  g_PQ[4 * NV];                // [h0P, h0Q, h1P, h1Q]
__device__ float4 g_coefpk[NV];                // {czp0, czn0, czp1, czn1}
__device__ float4 g_rowea[NV];                 // {ea0, ea20, ea1, ea21}
__device__ double g_sum[2];                    // sum, sumsq

// ---------------- K0: zero accumulators (every graph replay) ----------------
__global__ void k0_zero() {
    int i = blockIdx.x * 256 + threadIdx.x;
    if (i < 4 * NV) g_PQ[i] = 0.0f;
    if (i < 2) g_sum[i] = 0.0;
}

// ---------------- K1: fused SGEMM  C = x @ [W0 | W1 | Wres^T]  (+ fp16 epilogue) ----------------
__global__ __launch_bounds__(256) void k1_gemm(const float* __restrict__ x,
                                               const float* __restrict__ W,
                                               const float* __restrict__ Wres) {
    __shared__ float As[16][132];
    __shared__ float Bs[16][128];
    const int m0 = blockIdx.x * 128;
    const int which = blockIdx.y;
    const int tid = threadIdx.x;
    const int tx = tid & 15, ty = tid >> 4;

    float acc[8][8];
#pragma unroll
    for (int i = 0; i < 8; i++)
#pragma unroll
        for (int j = 0; j < 8; j++) acc[i][j] = 0.0f;

    const int mA = tid >> 1;
    const int kA = (tid & 1) * 8;

    for (int k0 = 0; k0 < DIN; k0 += 16) {
        {
            const float* src = x + (size_t)(m0 + mA) * DIN + k0 + kA;
            float4 v0 = *(const float4*)(src);
            float4 v1 = *(const float4*)(src + 4);
            As[kA + 0][mA] = v0.x; As[kA + 1][mA] = v0.y;
            As[kA + 2][mA] = v0.z; As[kA + 3][mA] = v0.w;
            As[kA + 4][mA] = v1.x; As[kA + 5][mA] = v1.y;
            As[kA + 6][mA] = v1.z; As[kA + 7][mA] = v1.w;
        }
        if (which < 2) {
            int k = tid >> 4, f = (tid & 15) * 8;
            const float* src = W + ((size_t)which * DIN + (k0 + k)) * FD + f;
            float4 v0 = *(const float4*)(src);
            float4 v1 = *(const float4*)(src + 4);
            *(float4*)&Bs[k][f] = v0;
            *(float4*)&Bs[k][f + 4] = v1;
        } else {
            int f = tid >> 1;
            const float* src = Wres + (size_t)f * DIN + k0 + kA;
            float4 v0 = *(const float4*)(src);
            float4 v1 = *(const float4*)(src + 4);
            Bs[kA + 0][f] = v0.x; Bs[kA + 1][f] = v0.y;
            Bs[kA + 2][f] = v0.z; Bs[kA + 3][f] = v0.w;
            Bs[kA + 4][f] = v1.x; Bs[kA + 5][f] = v1.y;
            Bs[kA + 6][f] = v1.z; Bs[kA + 7][f] = v1.w;
        }
        __syncthreads();

#pragma unroll
        for (int kk = 0; kk < 16; kk++) {
            float4 ra0 = *(const float4*)&As[kk][ty * 8];
            float4 ra1 = *(const float4*)&As[kk][ty * 8 + 4];
            float4 rb0 = *(const float4*)&Bs[kk][tx * 8];
            float4 rb1 = *(const float4*)&Bs[kk][tx * 8 + 4];
            float ra[8] = {ra0.x, ra0.y, ra0.z, ra0.w, ra1.x, ra1.y, ra1.z, ra1.w};
            float rb[8] = {rb0.x, rb0.y, rb0.z, rb0.w, rb1.x, rb1.y, rb1.z, rb1.w};
#pragma unroll
            for (int i = 0; i < 8; i++)
#pragma unroll
                for (int j = 0; j < 8; j++) acc[i][j] += ra[i] * rb[j];
        }
        __syncthreads();
    }

    float* dst = (which < 2) ? &g_proj[(size_t)which * NF] : g_res;
#pragma unroll
    for (int i = 0; i < 8; i++) {
        int row = m0 + ty * 8 + i;
        float4 w0 = make_float4(acc[i][0], acc[i][1], acc[i][2], acc[i][3]);
        float4 w1 = make_float4(acc[i][4], acc[i][5], acc[i][6], acc[i][7]);
        *(float4*)&dst[(size_t)row * FD + tx * 8]     = w0;
        *(float4*)&dst[(size_t)row * FD + tx * 8 + 4] = w1;
        if (which < 2) {
            __align__(16) __half2 hp[4];
            hp[0] = __floats2half2_rn(acc[i][0], acc[i][1]);
            hp[1] = __floats2half2_rn(acc[i][2], acc[i][3]);
            hp[2] = __floats2half2_rn(acc[i][4], acc[i][5]);
            hp[3] = __floats2half2_rn(acc[i][6], acc[i][7]);
            *(uint4*)((char*)g_projh + (size_t)row * 512 + which * 256 + tx * 16) = *(uint4*)hp;
        }
    }
}

// ---------------- K2: per-node dots + 8 exps (+ packed rowea/stgt2) ----------------
__global__ __launch_bounds__(256) void k2_scal(const float* __restrict__ asrc,
                                               const float* __restrict__ atgt) {
    int w = blockIdx.x * 8 + (threadIdx.x >> 5);
    int lane = threadIdx.x & 31;
    if (w >= 2 * NV) return;
    int h = w >> 13;
    const float* pr = &g_proj[(size_t)w * FD];
    const float* as = asrc + h * FD;
    const float* at = atgt + h * FD;
    float s1 = 0.0f, s2 = 0.0f;
#pragma unroll
    for (int j = 0; j < 4; j++) {
        float p = pr[lane + 32 * j];
        s1 += p * as[lane + 32 * j];
        s2 += p * at[lane + 32 * j];
    }
#pragma unroll
    for (int o = 16; o; o >>= 1) {
        s1 += __shfl_xor_sync(FULLMASK, s1, o);
        s2 += __shfl_xor_sync(FULLMASK, s2, o);
    }
    if (lane == 0) {
        float ea = expf(s1), ea2 = expf(0.2f * s1);
        g_ssrc[w] = s1; g_ea[w] = ea; g_ea2[w] = ea2;
        g_eb[w] = expf(s2); g_eb2[w] = expf(0.2f * s2);
        int n = w & (NV - 1);
        ((float2*)&g_rowea[n])[h] = make_float2(ea, ea2);
        ((float*)&g_stgt2[n])[h] = s2;
    }
}

// ---------------- K3: mask pass, 2 warps/row, 4 front-batched loads ----------------
__global__ __launch_bounds__(256) void k3_mask(const float4* __restrict__ conn,
                                               float4* __restrict__ outmask) {
    int w = blockIdx.x * 8 + (threadIdx.x >> 5);   // 0..16383
    int lane = threadIdx.x & 31;
    int m = w >> 1, half = w & 1;
    const float4* src = conn + (size_t)m * (NV / 4) + half * 1024;
    float4* dst = outmask + (size_t)m * (NV / 4) + half * 1024;
    unsigned short* cols = &g_cols[(size_t)m * MAXE + half * HMAX];
    int cnt = 0;
    for (int it = 0; it < 8; it++) {               // 8 outer x 4 batched x 128 floats
        float4 v[4];
#pragma unroll
        for (int j = 0; j < 4; j++) v[j] = src[it * 128 + j * 32 + lane];
#pragma unroll
        for (int j = 0; j < 4; j++) __stcs(&dst[it * 128 + j * 32 + lane], v[j]);
#pragma unroll
        for (int j = 0; j < 4; j++) {
            unsigned b0 = __ballot_sync(FULLMASK, v[j].x == 0.0f);
            unsigned b1 = __ballot_sync(FULLMASK, v[j].y == 0.0f);
            unsigned b2 = __ballot_sync(FULLMASK, v[j].z == 0.0f);
            unsigned b3 = __ballot_sync(FULLMASK, v[j].w == 0.0f);
            unsigned lt = (1u << lane) - 1u;
            int o = cnt + __popc(b0 & lt) + __popc(b1 & lt) + __popc(b2 & lt) + __popc(b3 & lt);
            int col0 = half * 4096 + it * 512 + j * 128 + lane * 4;
            if (v[j].x == 0.0f) { if (o < HMAX) cols[o] = (unsigned short)(col0);     o++; }
            if (v[j].y == 0.0f) { if (o < HMAX) cols[o] = (unsigned short)(col0 + 1); o++; }
            if (v[j].z == 0.0f) { if (o < HMAX) cols[o] = (unsigned short)(col0 + 2); o++; }
            if (v[j].w == 0.0f) { if (o < HMAX) cols[o] = (unsigned short)(col0 + 3); o++; }
            cnt += __popc(b0) + __popc(b1) + __popc(b2) + __popc(b3);
        }
    }
    if (lane == 0) g_rowcnt2[w] = min(cnt, HMAX);
}

// ---------------- K4: sign-split column sums P/Q, 4-edge batched (warp per sublist) ----------------
__global__ __launch_bounds__(256) void k4_z() {
    int w = blockIdx.x * 8 + (threadIdx.x >> 5);   // 0..16383
    int lane = threadIdx.x & 31;
    int m = w >> 1, half = w & 1;
    int cnt = g_rowcnt2[w];
    float ss0 = g_ssrc[m],      ea0 = g_ea[m],      ea20 = g_ea2[m];
    float ss1 = g_ssrc[NV + m], ea1 = g_ea[NV + m], ea21 = g_ea2[NV + m];
    unsigned short* cols = &g_cols[(size_t)m * MAXE + half * HMAX];
    for (int base = 0; base < cnt; base += 128) {
        unsigned c[4];
        float2 st[4];
        bool val[4];
#pragma unroll
        for (int j = 0; j < 4; j++) {
            int e = base + j * 32 + lane;
            val[j] = e < cnt;
            c[j] = val[j] ? (unsigned)cols[e] : 0u;
        }
#pragma unroll
        for (int j = 0; j < 4; j++)
            if (val[j]) st[j] = g_stgt2[c[j]];
#pragma unroll
        for (int j = 0; j < 4; j++) {
            if (!val[j]) continue;
            int n = (int)c[j];
            unsigned cc = c[j];
            if (ss0 + st[j].x > 0.0f) { atomicAdd(&g_PQ[n], ea0);          cc |= 0x4000u; }
            else                      { atomicAdd(&g_PQ[NV + n], ea20); }
            if (ss1 + st[j].y > 0.0f) { atomicAdd(&g_PQ[2 * NV + n], ea1); cc |= 0x2000u; }
            else                      { atomicAdd(&g_PQ[3 * NV + n], ea21); }
            cols[base + j * 32 + lane] = (unsigned short)cc;
        }
    }
}

// ---------------- K5: fold Z into packed per-column coefficients ----------------
__global__ void k5_cz() {
    int n = blockIdx.x * 256 + threadIdx.x;
    if (n >= NV) return;
    float Z0 = g_eb[n] * g_PQ[n] + g_eb2[n] * g_PQ[NV + n];
    float Z1 = g_eb[NV + n] * g_PQ[2 * NV + n] + g_eb2[NV + n] * g_PQ[3 * NV + n];
    g_coefpk[n] = make_float4(0.5f * g_eb[n] / Z0,       0.5f * g_eb2[n] / Z0,
                              0.5f * g_eb[NV + n] / Z1,  0.5f * g_eb2[NV + n] / Z1);
}

// ---------------- K6: gather SpMM, 4 warps/row (2 per sublist), fused stats ----------------
// grid 4096 x 256: 2 rows/block, lane-split heads within each warp.
__global__ __launch_bounds__(256) void k6_spmm() {
    __shared__ float  smrg[8][128];
    __shared__ double sred[2][2];
    const int tid = threadIdx.x, wid = tid >> 5, lane = tid & 31;
    const int rl = wid >> 2, sub = (wid >> 1) & 1, par = wid & 1;
    const int row = blockIdx.x * 2 + rl;
    const int cnt = g_rowcnt2[row * 2 + sub];
    const unsigned short* __restrict__ cp = &g_cols[(size_t)row * MAXE + sub * HMAX];
    const float4 re = __ldg(&g_rowea[row]);
    const bool h1 = lane >= 16;

    float acc[8];
#pragma unroll
    for (int j = 0; j < 8; j++) acc[j] = 0.0f;

#pragma unroll 4
    for (int e = par; e < cnt; e += 2) {
        const unsigned c = cp[e];
        const int n = (int)(c & 0x1FFFu);
        const float4 q = __ldg(&g_coefpk[n]);
        const float cf = h1 ? ((c & 0x2000u) ? re.z * q.z : re.w * q.w)
                            : ((c & 0x4000u) ? re.x * q.x : re.y * q.y);
        const uint4 hv = *(const uint4*)((const char*)g_projh + (size_t)n * 512 + lane * 16);
        const half2* hp = (const half2*)&hv;
#pragma unroll
        for (int j = 0; j < 4; j++) {
            float2 f = __half22float2(hp[j]);
            acc[2 * j]     += cf * f.x;
            acc[2 * j + 1] += cf * f.y;
        }
    }
    // merge head1 partials (lanes 16..31) into lanes 0..15, park in smem
#pragma unroll
    for (int j = 0; j < 8; j++) acc[j] += __shfl_down_sync(FULLMASK, acc[j], 16);
    if (lane < 16) {
#pragma unroll
        for (int j = 0; j < 8; j++) smrg[wid][lane * 8 + j] = acc[j];
    }
    __syncthreads();

    double s = 0.0, s2 = 0.0;
    if ((wid & 3) == 0) {                          // warps 0 and 4 finalize their row
        if (lane < 16) {
            float v[8];
#pragma unroll
            for (int j = 0; j < 8; j++) {
                int idx = lane * 8 + j;
                v[j] = smrg[wid][idx] + smrg[wid + 1][idx] + smrg[wid + 2][idx] + smrg[wid + 3][idx];
                double dv = (double)v[j];
                s += dv; s2 += dv * dv;
            }
            float* dp = &g_vals[(size_t)row * FD + lane * 8];
            *(float4*)dp       = make_float4(v[0], v[1], v[2], v[3]);
            *(float4*)(dp + 4) = make_float4(v[4], v[5], v[6], v[7]);
        }
#pragma unroll
        for (int o = 8; o; o >>= 1) {
            s  += __shfl_down_sync(FULLMASK, s, o);
            s2 += __shfl_down_sync(FULLMASK, s2, o);
        }
        if (lane == 0) { sred[0][rl] = s; sred[1][rl] = s2; }
    }
    __syncthreads();
    if (tid == 0) {
        atomicAdd(&g_sum[0], sred[0][0] + sred[0][1]);
        atomicAdd(&g_sum[1], sred[1][0] + sred[1][1]);
    }
}

// ---------------- K8: normalize + residual + ELU ----------------
__global__ void k8_final(float* __restrict__ out) {
    int i = blockIdx.x * 256 + threadIdx.x;
    if (i >= NF) return;
    double mu_d = g_sum[0] / (double)NF;
    double var_d = g_sum[1] / (double)NF - mu_d * mu_d;
    float mu = (float)mu_d;
    float inv = rsqrtf((float)var_d + 1e-5f);
    float v = (g_vals[i] - mu) * inv + g_res[i];
    out[i] = v > 0.0f ? v : expm1f(v);
}

// ---------------- launch: forked capture (zero+GEMM branch ‖ mask branch) ----------------
extern "C" void kernel_launch(void* const* d_in, const int* in_sizes, int n_in,
                              void* d_out, int out_size) {
    const float* x    = (const float*)d_in[0];
    const float* conn = (const float*)d_in[1];
    const float* W    = (const float*)d_in[2];
    const float* asrc = (const float*)d_in[3];
    const float* atgt = (const float*)d_in[4];
    const float* wres = (const float*)d_in[5];
    float* out = (float*)d_out;
    float* outmask = out + NF;

    static cudaStream_t sA = nullptr, sB = nullptr;
    static cudaEvent_t evF = nullptr, evA = nullptr, evB = nullptr;
    if (!sA) {
        cudaStreamCreateWithFlags(&sA, cudaStreamNonBlocking);
        cudaStreamCreateWithFlags(&sB, cudaStreamNonBlocking);
        cudaEventCreateWithFlags(&evF, cudaEventDisableTiming);
        cudaEventCreateWithFlags(&evA, cudaEventDisableTiming);
        cudaEventCreateWithFlags(&evB, cudaEventDisableTiming);
    }

    // fork
    cudaEventRecord(evF, 0);
    cudaStreamWaitEvent(sA, evF, 0);
    cudaStreamWaitEvent(sB, evF, 0);

    // branch A (shorter): zero accumulators + GEMM + per-node scalars
    k0_zero<<<128, 256, 0, sA>>>();
    k1_gemm<<<dim3(64, 3), 256, 0, sA>>>(x, W, wres);
    k2_scal<<<2048, 256, 0, sA>>>(asrc, atgt);
    cudaEventRecord(evA, sA);

    // branch B (longer, DRAM-bound): mask stream
    k3_mask<<<2048, 256, 0, sB>>>((const float4*)conn, (float4*)outmask);
    cudaEventRecord(evB, sB);

    // join on legacy stream
    cudaStreamWaitEvent(0, evA, 0);
    cudaStreamWaitEvent(0, evB, 0);

    k4_z<<<2048, 256>>>();
    k5_cz<<<32, 256>>>();
    k6_spmm<<<4096, 256>>>();
    k8_final<<<NF / 256, 256>>>(out);
}